// round 10
// baseline (speedup 1.0000x reference)
#include <cuda_runtime.h>
#include <cuda_fp16.h>
#include <cstdint>

// ---------------- problem constants ----------------
constexpr int KC = 128, KH = 10, KW = 4;
constexpr int H = 100, W = 64;
constexpr int NH = 10, NW = 16;
constexpr int M = NH * NW;                 // 160 q rows
constexpr int HK = H - KH + 1;             // 91
constexpr int WK = W - KW + 1;             // 61
constexpr int NKV = HK * WK;               // 5551
constexpr int NPAD = 5632;                 // 88*64
constexpr int D = KC * KH * KW;            // 5120

// ---------------- scratch ----------------
__device__ __half g_kv[(size_t)NPAD * D];      // [n][d] d-contig
__device__ __half g_q[M * D];
__device__ __half g_attn[M * NPAD];            // unnormalized exp(scores), pads = 0
__device__ float  g_inv[M];                    // 1 / rowsum

// ---------------- ptx helpers ----------------
__device__ __forceinline__ uint32_t smem_u32(const void* p) {
    return (uint32_t)__cvta_generic_to_shared(p);
}
__device__ __forceinline__ void ldsm_x4(uint32_t& r0, uint32_t& r1, uint32_t& r2,
                                        uint32_t& r3, uint32_t a) {
    asm volatile("ldmatrix.sync.aligned.m8n8.x4.shared.b16 {%0,%1,%2,%3}, [%4];"
                 : "=r"(r0), "=r"(r1), "=r"(r2), "=r"(r3) : "r"(a));
}
__device__ __forceinline__ void ldsm_x4_t(uint32_t& r0, uint32_t& r1, uint32_t& r2,
                                          uint32_t& r3, uint32_t a) {
    asm volatile("ldmatrix.sync.aligned.m8n8.x4.trans.shared.b16 {%0,%1,%2,%3}, [%4];"
                 : "=r"(r0), "=r"(r1), "=r"(r2), "=r"(r3) : "r"(a));
}
__device__ __forceinline__ void mma16816(float* c, const uint32_t* a, const uint32_t* b) {
    asm volatile("mma.sync.aligned.m16n8k16.row.col.f32.f16.f16.f32 "
                 "{%0,%1,%2,%3}, {%4,%5,%6,%7}, {%8,%9}, {%0,%1,%2,%3};"
                 : "+f"(c[0]), "+f"(c[1]), "+f"(c[2]), "+f"(c[3])
                 : "r"(a[0]), "r"(a[1]), "r"(a[2]), "r"(a[3]),
                   "r"(b[0]), "r"(b[1]));
}
__device__ __forceinline__ void cpasync16(uint32_t s, const void* g) {
    asm volatile("cp.async.cg.shared.global [%0], [%1], 16;" :: "r"(s), "l"(g));
}
#define CP_COMMIT() asm volatile("cp.async.commit_group;")
#define CP_WAIT(n)  asm volatile("cp.async.wait_group %0;" :: "n"(n))

// ---------------- kernel 1: expand z2 -> kv fp16 ----------------
__global__ void build_kv_kernel(const float* __restrict__ z2) {
    constexpr int TOTAL = NKV * KC * KH;
    constexpr int PADG  = (NPAD - NKV) * (D / 4);
    int idx = blockIdx.x * blockDim.x + threadIdx.x;
    if (idx < TOTAL) {
        int n   = idx / (KC * KH);
        int rem = idx - n * (KC * KH);
        int c   = rem / KH;
        int i   = rem - c * KH;
        int h   = n / WK;
        int w   = n - h * WK;
        const float* src = z2 + (c * H + h + i) * W + w;
        __half2 p0 = __floats2half2_rn(src[0], src[1]);
        __half2 p1 = __floats2half2_rn(src[2], src[3]);
        uint2 v;
        v.x = *reinterpret_cast<uint32_t*>(&p0);
        v.y = *reinterpret_cast<uint32_t*>(&p1);
        *reinterpret_cast<uint2*>(&g_kv[(size_t)n * D + (c * KH + i) * KW]) = v;
    } else if (idx < TOTAL + PADG) {
        int p   = idx - TOTAL;
        int pr  = p / (D / 4);
        int off = (p - pr * (D / 4)) * 4;
        *reinterpret_cast<uint2*>(&g_kv[(size_t)(NKV + pr) * D + off]) = make_uint2(0u, 0u);
    }
}

// ---------------- kernel 2: q patches -> fp16 ----------------
__global__ void build_q_kernel(const float* __restrict__ z1) {
    constexpr int TOTAL = M * KC * KH;
    int idx = blockIdx.x * blockDim.x + threadIdx.x;
    if (idx >= TOTAL) return;
    int m   = idx / (KC * KH);
    int rem = idx - m * (KC * KH);
    int c   = rem / KH;
    int i   = rem - c * KH;
    int ih  = m >> 4;
    int iw  = m & 15;
    const float4 f = *reinterpret_cast<const float4*>(
        z1 + (c * H + ih * KH + i) * W + iw * KW);
    __half2 p0 = __floats2half2_rn(f.x, f.y);
    __half2 p1 = __floats2half2_rn(f.z, f.w);
    uint2 v;
    v.x = *reinterpret_cast<uint32_t*>(&p0);
    v.y = *reinterpret_cast<uint32_t*>(&p1);
    *reinterpret_cast<uint2*>(&g_q[m * D + (c * KH + i) * KW]) = v;
}

// -------- GEMM tiling: CTA 32(M) x 64(N), 64 threads = 2 warps (32x32 each) ----
constexpr int BM  = 32;
constexpr int BN  = 64;
constexpr int BK  = 64;
constexpr int LDS = 72;
constexpr int STAGES = 4;
constexpr int A_HALVES = BM * LDS;               // 2304
constexpr int B_HALVES = BN * LDS;               // 4608
constexpr int STAGE_HALVES = A_HALVES + B_HALVES;
constexpr int SMEM_BYTES = STAGES * STAGE_HALVES * 2;   // 55296

// ------ kernel 3: attn_unnorm = exp(q @ kv^T / D), pads masked to 0 ------
__global__ __launch_bounds__(64, 4) void gemm_qk_kernel() {
    extern __shared__ __align__(16) __half sm[];
    const int n0   = blockIdx.x * BN;
    const int m0   = blockIdx.y * BM;
    const int tid  = threadIdx.x;
    const int wn   = tid >> 5, lane = tid & 31;  // 2 warps side by side in N
    constexpr int KT = D / BK;                   // 80

    auto load_stage = [&](int s, int kt) {
        const int k0 = kt * BK;
        __half* As = sm + s * STAGE_HALVES;
        __half* Bs = As + A_HALVES;
#pragma unroll
        for (int i = 0; i < 4; i++) {            // A: 256 chunks / 64 thr
            int t = tid + i * 64;
            int r = t >> 3, c8 = (t & 7) << 3;
            cpasync16(smem_u32(&As[r * LDS + c8]),
                      &g_q[(m0 + r) * D + k0 + c8]);
        }
#pragma unroll
        for (int i = 0; i < 8; i++) {            // B: 512 chunks
            int t = tid + i * 64;
            int r = t >> 3, c8 = (t & 7) << 3;
            cpasync16(smem_u32(&Bs[r * LDS + c8]),
                      &g_kv[(size_t)(n0 + r) * D + k0 + c8]);
        }
    };

#pragma unroll
    for (int s = 0; s < STAGES - 1; s++) { load_stage(s, s); CP_COMMIT(); }

    float acc[2][4][4] = {};

    for (int kt = 0; kt < KT; kt++) {
        CP_WAIT(STAGES - 2);
        __syncthreads();
        int nxt = kt + STAGES - 1;
        if (nxt < KT) load_stage(nxt & (STAGES - 1), nxt);
        CP_COMMIT();

        const __half* As = sm + (kt & (STAGES - 1)) * STAGE_HALVES;
        const __half* Bs = As + A_HALVES;
#pragma unroll
        for (int ks = 0; ks < BK / 16; ks++) {
            uint32_t a[2][4], b[4][2];
#pragma unroll
            for (int mi = 0; mi < 2; mi++) {
                int r = mi * 16 + (lane & 15);
                int c = ks * 16 + (lane >> 4) * 8;
                ldsm_x4(a[mi][0], a[mi][1], a[mi][2], a[mi][3],
                        smem_u32(&As[r * LDS + c]));
            }
#pragma unroll
            for (int nb = 0; nb < 2; nb++) {
                int r = wn * 32 + nb * 16 + (lane & 7) + (lane >> 4) * 8;
                int c = ks * 16 + ((lane >> 3) & 1) * 8;
                uint32_t r0, r1, r2, r3;
                ldsm_x4(r0, r1, r2, r3, smem_u32(&Bs[r * LDS + c]));
                b[nb * 2][0] = r0; b[nb * 2][1] = r1;
                b[nb * 2 + 1][0] = r2; b[nb * 2 + 1][1] = r3;
            }
#pragma unroll
            for (int mi = 0; mi < 2; mi++)
#pragma unroll
                for (int ni = 0; ni < 4; ni++)
                    mma16816(acc[mi][ni], a[mi], b[ni]);
        }
    }

    // epilogue: p = exp(s/D) (no max subtraction: |s/D| < ~0.1), mask pad cols
    const float scale = 1.0f / (float)D;
#pragma unroll
    for (int mi = 0; mi < 2; mi++)
#pragma unroll
        for (int ni = 0; ni < 4; ni++) {
            int row = m0 + mi * 16 + (lane >> 2);
            int col = n0 + wn * 32 + ni * 8 + ((lane & 3) << 1);
            float p00 = (col     < NKV) ? __expf(acc[mi][ni][0] * scale) : 0.f;
            float p01 = (col + 1 < NKV) ? __expf(acc[mi][ni][1] * scale) : 0.f;
            float p10 = (col     < NKV) ? __expf(acc[mi][ni][2] * scale) : 0.f;
            float p11 = (col + 1 < NKV) ? __expf(acc[mi][ni][3] * scale) : 0.f;
            *reinterpret_cast<__half2*>(&g_attn[row * NPAD + col]) =
                __floats2half2_rn(p00, p01);
            *reinterpret_cast<__half2*>(&g_attn[(row + 8) * NPAD + col]) =
                __floats2half2_rn(p10, p11);
        }
}

// ---------------- kernel 4: row sums -> g_inv (deterministic) ----------------
__global__ __launch_bounds__(512) void rowsum_kernel() {
    __shared__ float red[512];
    const int m   = blockIdx.x;
    const int tid = threadIdx.x;
    float sum = 0.f;
    for (int n = tid * 2; n < NPAD; n += 1024) {     // pads are 0, safe to include
        __half2 h2 = *reinterpret_cast<const __half2*>(&g_attn[m * NPAD + n]);
        float2 f2 = __half22float2(h2);
        sum += f2.x + f2.y;
    }
    red[tid] = sum;
    __syncthreads();
    for (int s = 256; s > 0; s >>= 1) {
        if (tid < s) red[tid] += red[tid + s];
        __syncthreads();
    }
    if (tid == 0) g_inv[m] = 1.0f / red[0];
}

// ---------------- kernel 5: out = (attn_unnorm @ kv) * inv[row] ----------------
__device__ __forceinline__ void store_out(float* __restrict__ out, int m, int d, float v) {
    int c   = d / 40;
    int rem = d - c * 40;
    int i   = rem >> 2;
    int j   = rem & 3;
    int ih  = m >> 4;
    int iw  = m & 15;
    out[(c * H + ih * KH + i) * W + iw * KW + j] = v;
}

__global__ __launch_bounds__(64, 4) void gemm_av_kernel(float* __restrict__ out) {
    extern __shared__ __align__(16) __half sm[];
    const int n0   = blockIdx.x * BN;            // over D
    const int m0   = blockIdx.y * BM;
    const int tid  = threadIdx.x;
    const int wn   = tid >> 5, lane = tid & 31;
    constexpr int KT = NPAD / BK;                // 88

    auto load_stage = [&](int s, int kt) {
        const int k0 = kt * BK;
        __half* As = sm + s * STAGE_HALVES;
        __half* Bs = As + A_HALVES;
#pragma unroll
        for (int i = 0; i < 4; i++) {            // A: 256 chunks (k-contig rows)
            int t = tid + i * 64;
            int r = t >> 3, c8 = (t & 7) << 3;
            cpasync16(smem_u32(&As[r * LDS + c8]),
                      &g_attn[(m0 + r) * NPAD + k0 + c8]);
        }
#pragma unroll
        for (int i = 0; i < 8; i++) {            // B: 64 k-rows x 8 chunks (n-contig)
            int t = tid + i * 64;
            int r = t >> 3, c8 = (t & 7) << 3;
            cpasync16(smem_u32(&Bs[r * LDS + c8]),
                      &g_kv[(size_t)(k0 + r) * D + n0 + c8]);
        }
    };

#pragma unroll
    for (int s = 0; s < STAGES - 1; s++) { load_stage(s, s); CP_COMMIT(); }

    float acc[2][4][4] = {};

    for (int kt = 0; kt < KT; kt++) {
        CP_WAIT(STAGES - 2);
        __syncthreads();
        int nxt = kt + STAGES - 1;
        if (nxt < KT) load_stage(nxt & (STAGES - 1), nxt);
        CP_COMMIT();

        const __half* As = sm + (kt & (STAGES - 1)) * STAGE_HALVES;
        const __half* Bs = As + A_HALVES;
#pragma unroll
        for (int ks = 0; ks < BK / 16; ks++) {
            uint32_t a[2][4], b[4][2];
#pragma unroll
            for (int mi = 0; mi < 2; mi++) {
                int r = mi * 16 + (lane & 15);
                int c = ks * 16 + (lane >> 4) * 8;
                ldsm_x4(a[mi][0], a[mi][1], a[mi][2], a[mi][3],
                        smem_u32(&As[r * LDS + c]));
            }
#pragma unroll
            for (int nb = 0; nb < 2; nb++) {
                int r = ks * 16 + (lane & 7) + ((lane >> 3) & 1) * 8;
                int c = wn * 32 + nb * 16 + (lane >> 4) * 8;
                uint32_t r0, r1, r2, r3;
                ldsm_x4_t(r0, r1, r2, r3, smem_u32(&Bs[r * LDS + c]));
                b[nb * 2][0] = r0; b[nb * 2][1] = r1;
                b[nb * 2 + 1][0] = r2; b[nb * 2 + 1][1] = r3;
            }
#pragma unroll
            for (int mi = 0; mi < 2; mi++)
#pragma unroll
                for (int ni = 0; ni < 4; ni++)
                    mma16816(acc[mi][ni], a[mi], b[ni]);
        }
    }

#pragma unroll
    for (int mi = 0; mi < 2; mi++) {
        int row = m0 + mi * 16 + (lane >> 2);
        const float inv0 = g_inv[row];
        const float inv1 = g_inv[row + 8];
#pragma unroll
        for (int ni = 0; ni < 4; ni++) {
            int col = n0 + wn * 32 + ni * 8 + ((lane & 3) << 1);
            store_out(out, row,     col,     acc[mi][ni][0] * inv0);
            store_out(out, row,     col + 1, acc[mi][ni][1] * inv0);
            store_out(out, row + 8, col,     acc[mi][ni][2] * inv1);
            store_out(out, row + 8, col + 1, acc[mi][ni][3] * inv1);
        }
    }
}

// ---------------- launch ----------------
extern "C" void kernel_launch(void* const* d_in, const int* in_sizes, int n_in,
                              void* d_out, int out_size) {
    const float* z1 = (const float*)d_in[0];
    const float* z2 = (const float*)d_in[1];
    float* out = (float*)d_out;

    cudaFuncSetAttribute(gemm_qk_kernel,
                         cudaFuncAttributeMaxDynamicSharedMemorySize, SMEM_BYTES);
    cudaFuncSetAttribute(gemm_av_kernel,
                         cudaFuncAttributeMaxDynamicSharedMemorySize, SMEM_BYTES);

    build_q_kernel<<<800, 256>>>(z1);
    build_kv_kernel<<<28160, 256>>>(z2);
    gemm_qk_kernel<<<dim3(NPAD / BN, M / BM), 64, SMEM_BYTES>>>();   // 88x5 = 440
    rowsum_kernel<<<M, 512>>>();
    gemm_av_kernel<<<dim3(D / BN, M / BM), 64, SMEM_BYTES>>>(out);   // 80x5 = 400
}

// round 11
// speedup vs baseline: 1.0294x; 1.0294x over previous
#include <cuda_runtime.h>
#include <cuda_fp16.h>
#include <cstdint>

// ---------------- problem constants ----------------
constexpr int KC = 128, KH = 10, KW = 4;
constexpr int H = 100, W = 64;
constexpr int NH = 10, NW = 16;
constexpr int M = NH * NW;                 // 160 q rows
constexpr int HK = H - KH + 1;             // 91
constexpr int WK = W - KW + 1;             // 61
constexpr int NKV = HK * WK;               // 5551
constexpr int NPAD = 5632;                 // 88*64
constexpr int D = KC * KH * KW;            // 5120

// ---------------- scratch ----------------
__device__ __half g_kv[(size_t)NPAD * D];      // [n][d] d-contig
__device__ __half g_q[M * D];
__device__ __half g_attn[M * NPAD];            // unnormalized exp(scores), pads = 0
__device__ float  g_rsum[M][4];                // partial row sums (4 chunks)

// ---------------- ptx helpers ----------------
__device__ __forceinline__ uint32_t smem_u32(const void* p) {
    return (uint32_t)__cvta_generic_to_shared(p);
}
__device__ __forceinline__ void ldsm_x4(uint32_t& r0, uint32_t& r1, uint32_t& r2,
                                        uint32_t& r3, uint32_t a) {
    asm volatile("ldmatrix.sync.aligned.m8n8.x4.shared.b16 {%0,%1,%2,%3}, [%4];"
                 : "=r"(r0), "=r"(r1), "=r"(r2), "=r"(r3) : "r"(a));
}
__device__ __forceinline__ void ldsm_x4_t(uint32_t& r0, uint32_t& r1, uint32_t& r2,
                                          uint32_t& r3, uint32_t a) {
    asm volatile("ldmatrix.sync.aligned.m8n8.x4.trans.shared.b16 {%0,%1,%2,%3}, [%4];"
                 : "=r"(r0), "=r"(r1), "=r"(r2), "=r"(r3) : "r"(a));
}
__device__ __forceinline__ void mma16816(float* c, const uint32_t* a, const uint32_t* b) {
    asm volatile("mma.sync.aligned.m16n8k16.row.col.f32.f16.f16.f32 "
                 "{%0,%1,%2,%3}, {%4,%5,%6,%7}, {%8,%9}, {%0,%1,%2,%3};"
                 : "+f"(c[0]), "+f"(c[1]), "+f"(c[2]), "+f"(c[3])
                 : "r"(a[0]), "r"(a[1]), "r"(a[2]), "r"(a[3]),
                   "r"(b[0]), "r"(b[1]));
}
__device__ __forceinline__ void cpasync16(uint32_t s, const void* g) {
    asm volatile("cp.async.cg.shared.global [%0], [%1], 16;" :: "r"(s), "l"(g));
}
__device__ __forceinline__ void cpasync16_ca(uint32_t s, const void* g) {
    asm volatile("cp.async.ca.shared.global [%0], [%1], 16;" :: "r"(s), "l"(g));
}
#define CP_COMMIT() asm volatile("cp.async.commit_group;")
#define CP_WAIT(n)  asm volatile("cp.async.wait_group %0;" :: "n"(n))

// ---------------- kernel 1: expand z2 -> kv fp16 ----------------
__global__ void build_kv_kernel(const float* __restrict__ z2) {
    constexpr int TOTAL = NKV * KC * KH;
    constexpr int PADG  = (NPAD - NKV) * (D / 4);
    int idx = blockIdx.x * blockDim.x + threadIdx.x;
    if (idx < TOTAL) {
        int n   = idx / (KC * KH);
        int rem = idx - n * (KC * KH);
        int c   = rem / KH;
        int i   = rem - c * KH;
        int h   = n / WK;
        int w   = n - h * WK;
        const float* src = z2 + (c * H + h + i) * W + w;
        __half2 p0 = __floats2half2_rn(src[0], src[1]);
        __half2 p1 = __floats2half2_rn(src[2], src[3]);
        uint2 v;
        v.x = *reinterpret_cast<uint32_t*>(&p0);
        v.y = *reinterpret_cast<uint32_t*>(&p1);
        *reinterpret_cast<uint2*>(&g_kv[(size_t)n * D + (c * KH + i) * KW]) = v;
    } else if (idx < TOTAL + PADG) {
        int p   = idx - TOTAL;
        int pr  = p / (D / 4);
        int off = (p - pr * (D / 4)) * 4;
        *reinterpret_cast<uint2*>(&g_kv[(size_t)(NKV + pr) * D + off]) = make_uint2(0u, 0u);
    }
}

// ---------------- kernel 2: q patches -> fp16 ----------------
__global__ void build_q_kernel(const float* __restrict__ z1) {
    constexpr int TOTAL = M * KC * KH;
    int idx = blockIdx.x * blockDim.x + threadIdx.x;
    if (idx >= TOTAL) return;
    int m   = idx / (KC * KH);
    int rem = idx - m * (KC * KH);
    int c   = rem / KH;
    int i   = rem - c * KH;
    int ih  = m >> 4;
    int iw  = m & 15;
    const float4 f = *reinterpret_cast<const float4*>(
        z1 + (c * H + ih * KH + i) * W + iw * KW);
    __half2 p0 = __floats2half2_rn(f.x, f.y);
    __half2 p1 = __floats2half2_rn(f.z, f.w);
    uint2 v;
    v.x = *reinterpret_cast<uint32_t*>(&p0);
    v.y = *reinterpret_cast<uint32_t*>(&p1);
    *reinterpret_cast<uint2*>(&g_q[m * D + (c * KH + i) * KW]) = v;
}

// -------- GEMM tiling: CTA 32(M) x 64(N), 64 threads = 2 warps (32x32 each) ----
constexpr int BM  = 32;
constexpr int BN  = 64;
constexpr int BK  = 64;
constexpr int LDS = 72;
constexpr int STAGES = 4;
constexpr int A_HALVES = BM * LDS;               // 2304
constexpr int B_HALVES = BN * LDS;               // 4608
constexpr int STAGE_HALVES = A_HALVES + B_HALVES;
constexpr int SMEM_BYTES = STAGES * STAGE_HALVES * 2;   // 55296

// ------ kernel 3: attn_unnorm = exp(q @ kv^T / D), pads masked to 0 ------
__global__ __launch_bounds__(64, 4) void gemm_qk_kernel() {
    extern __shared__ __align__(16) __half sm[];
    const int n0   = blockIdx.x * BN;
    const int m0   = blockIdx.y * BM;
    const int tid  = threadIdx.x;
    const int wn   = tid >> 5, lane = tid & 31;
    constexpr int KT = D / BK;                   // 80

    auto load_stage = [&](int s, int kt) {
        const int k0 = kt * BK;
        __half* As = sm + s * STAGE_HALVES;
        __half* Bs = As + A_HALVES;
#pragma unroll
        for (int i = 0; i < 4; i++) {            // A: 256 chunks (L1-cached: reused by 88 CTAs)
            int t = tid + i * 64;
            int r = t >> 3, c8 = (t & 7) << 3;
            cpasync16_ca(smem_u32(&As[r * LDS + c8]),
                         &g_q[(m0 + r) * D + k0 + c8]);
        }
#pragma unroll
        for (int i = 0; i < 8; i++) {            // B: 512 chunks
            int t = tid + i * 64;
            int r = t >> 3, c8 = (t & 7) << 3;
            cpasync16(smem_u32(&Bs[r * LDS + c8]),
                      &g_kv[(size_t)(n0 + r) * D + k0 + c8]);
        }
    };

#pragma unroll
    for (int s = 0; s < STAGES - 1; s++) { load_stage(s, s); CP_COMMIT(); }

    float acc[2][4][4] = {};
    uint32_t a[2][2][4], b[2][4][2];             // double-buffered fragments

    auto load_frags = [&](const __half* As, const __half* Bs, int ks, int buf) {
#pragma unroll
        for (int mi = 0; mi < 2; mi++) {
            int r = mi * 16 + (lane & 15);
            int c = ks * 16 + (lane >> 4) * 8;
            ldsm_x4(a[buf][mi][0], a[buf][mi][1], a[buf][mi][2], a[buf][mi][3],
                    smem_u32(&As[r * LDS + c]));
        }
#pragma unroll
        for (int nb = 0; nb < 2; nb++) {
            int r = wn * 32 + nb * 16 + (lane & 7) + (lane >> 4) * 8;
            int c = ks * 16 + ((lane >> 3) & 1) * 8;
            uint32_t r0, r1, r2, r3;
            ldsm_x4(r0, r1, r2, r3, smem_u32(&Bs[r * LDS + c]));
            b[buf][nb * 2][0] = r0; b[buf][nb * 2][1] = r1;
            b[buf][nb * 2 + 1][0] = r2; b[buf][nb * 2 + 1][1] = r3;
        }
    };

    for (int kt = 0; kt < KT; kt++) {
        CP_WAIT(STAGES - 2);
        __syncthreads();
        int nxt = kt + STAGES - 1;
        if (nxt < KT) load_stage(nxt & (STAGES - 1), nxt);
        CP_COMMIT();

        const __half* As = sm + (kt & (STAGES - 1)) * STAGE_HALVES;
        const __half* Bs = As + A_HALVES;
        load_frags(As, Bs, 0, 0);
#pragma unroll
        for (int ks = 0; ks < BK / 16; ks++) {
            const int cur = ks & 1;
            if (ks < BK / 16 - 1) load_frags(As, Bs, ks + 1, cur ^ 1);
#pragma unroll
            for (int mi = 0; mi < 2; mi++)
#pragma unroll
                for (int ni = 0; ni < 4; ni++)
                    mma16816(acc[mi][ni], a[cur][mi], b[cur][ni]);
        }
    }

    // epilogue: p = exp(s/D) (no max subtraction: |s/D| small), mask pad cols
    const float scale = 1.0f / (float)D;
#pragma unroll
    for (int mi = 0; mi < 2; mi++)
#pragma unroll
        for (int ni = 0; ni < 4; ni++) {
            int row = m0 + mi * 16 + (lane >> 2);
            int col = n0 + wn * 32 + ni * 8 + ((lane & 3) << 1);
            float p00 = (col     < NKV) ? __expf(acc[mi][ni][0] * scale) : 0.f;
            float p01 = (col + 1 < NKV) ? __expf(acc[mi][ni][1] * scale) : 0.f;
            float p10 = (col     < NKV) ? __expf(acc[mi][ni][2] * scale) : 0.f;
            float p11 = (col + 1 < NKV) ? __expf(acc[mi][ni][3] * scale) : 0.f;
            *reinterpret_cast<__half2*>(&g_attn[row * NPAD + col]) =
                __floats2half2_rn(p00, p01);
            *reinterpret_cast<__half2*>(&g_attn[(row + 8) * NPAD + col]) =
                __floats2half2_rn(p10, p11);
        }
}

// -------- kernel 4: partial row sums (grid 4 x 160, deterministic) --------
__global__ __launch_bounds__(128) void rowsum_kernel() {
    __shared__ float red[128];
    const int part = blockIdx.x;                 // 0..3
    const int m    = blockIdx.y;
    const int tid  = threadIdx.x;
    constexpr int CHUNK = NPAD / 4;              // 1408 halves
    const int base = m * NPAD + part * CHUNK;
    float sum = 0.f;
    for (int n = tid * 2; n < CHUNK; n += 256) {
        __half2 h2 = *reinterpret_cast<const __half2*>(&g_attn[base + n]);
        float2 f2 = __half22float2(h2);
        sum += f2.x + f2.y;
    }
    red[tid] = sum;
    __syncthreads();
    for (int s = 64; s > 0; s >>= 1) {
        if (tid < s) red[tid] += red[tid + s];
        __syncthreads();
    }
    if (tid == 0) g_rsum[m][part] = red[0];
}

// ---------------- kernel 5: out = (attn_unnorm @ kv) * inv[row] ----------------
__device__ __forceinline__ void store_out(float* __restrict__ out, int m, int d, float v) {
    int c   = d / 40;
    int rem = d - c * 40;
    int i   = rem >> 2;
    int j   = rem & 3;
    int ih  = m >> 4;
    int iw  = m & 15;
    out[(c * H + ih * KH + i) * W + iw * KW + j] = v;
}

__global__ __launch_bounds__(64, 4) void gemm_av_kernel(float* __restrict__ out) {
    extern __shared__ __align__(16) __half sm[];
    const int n0   = blockIdx.x * BN;            // over D
    const int m0   = blockIdx.y * BM;
    const int tid  = threadIdx.x;
    const int wn   = tid >> 5, lane = tid & 31;
    constexpr int KT = NPAD / BK;                // 88

    auto load_stage = [&](int s, int kt) {
        const int k0 = kt * BK;
        __half* As = sm + s * STAGE_HALVES;
        __half* Bs = As + A_HALVES;
#pragma unroll
        for (int i = 0; i < 4; i++) {            // A: attn rows (L1-cached: reused by 80 CTAs)
            int t = tid + i * 64;
            int r = t >> 3, c8 = (t & 7) << 3;
            cpasync16_ca(smem_u32(&As[r * LDS + c8]),
                         &g_attn[(m0 + r) * NPAD + k0 + c8]);
        }
#pragma unroll
        for (int i = 0; i < 8; i++) {            // B: 64 k-rows x 8 chunks (n-contig)
            int t = tid + i * 64;
            int r = t >> 3, c8 = (t & 7) << 3;
            cpasync16(smem_u32(&Bs[r * LDS + c8]),
                      &g_kv[(size_t)(k0 + r) * D + n0 + c8]);
        }
    };

#pragma unroll
    for (int s = 0; s < STAGES - 1; s++) { load_stage(s, s); CP_COMMIT(); }

    float acc[2][4][4] = {};
    uint32_t a[2][2][4], b[2][4][2];

    auto load_frags = [&](const __half* As, const __half* Bs, int ks, int buf) {
#pragma unroll
        for (int mi = 0; mi < 2; mi++) {
            int r = mi * 16 + (lane & 15);
            int c = ks * 16 + (lane >> 4) * 8;
            ldsm_x4(a[buf][mi][0], a[buf][mi][1], a[buf][mi][2], a[buf][mi][3],
                    smem_u32(&As[r * LDS + c]));
        }
#pragma unroll
        for (int nb = 0; nb < 2; nb++) {
            int r = ks * 16 + (lane & 7) + ((lane >> 3) & 1) * 8;
            int c = wn * 32 + nb * 16 + (lane >> 4) * 8;
            uint32_t r0, r1, r2, r3;
            ldsm_x4_t(r0, r1, r2, r3, smem_u32(&Bs[r * LDS + c]));
            b[buf][nb * 2][0] = r0; b[buf][nb * 2][1] = r1;
            b[buf][nb * 2 + 1][0] = r2; b[buf][nb * 2 + 1][1] = r3;
        }
    };

    for (int kt = 0; kt < KT; kt++) {
        CP_WAIT(STAGES - 2);
        __syncthreads();
        int nxt = kt + STAGES - 1;
        if (nxt < KT) load_stage(nxt & (STAGES - 1), nxt);
        CP_COMMIT();

        const __half* As = sm + (kt & (STAGES - 1)) * STAGE_HALVES;
        const __half* Bs = As + A_HALVES;
        load_frags(As, Bs, 0, 0);
#pragma unroll
        for (int ks = 0; ks < BK / 16; ks++) {
            const int cur = ks & 1;
            if (ks < BK / 16 - 1) load_frags(As, Bs, ks + 1, cur ^ 1);
#pragma unroll
            for (int mi = 0; mi < 2; mi++)
#pragma unroll
                for (int ni = 0; ni < 4; ni++)
                    mma16816(acc[mi][ni], a[cur][mi], b[cur][ni]);
        }
    }

#pragma unroll
    for (int mi = 0; mi < 2; mi++) {
        int row = m0 + mi * 16 + (lane >> 2);
        const float inv0 = 1.0f / (g_rsum[row][0] + g_rsum[row][1] +
                                   g_rsum[row][2] + g_rsum[row][3]);
        const float inv1 = 1.0f / (g_rsum[row + 8][0] + g_rsum[row + 8][1] +
                                   g_rsum[row + 8][2] + g_rsum[row + 8][3]);
#pragma unroll
        for (int ni = 0; ni < 4; ni++) {
            int col = n0 + wn * 32 + ni * 8 + ((lane & 3) << 1);
            store_out(out, row,     col,     acc[mi][ni][0] * inv0);
            store_out(out, row,     col + 1, acc[mi][ni][1] * inv0);
            store_out(out, row + 8, col,     acc[mi][ni][2] * inv1);
            store_out(out, row + 8, col + 1, acc[mi][ni][3] * inv1);
        }
    }
}

// ---------------- launch ----------------
extern "C" void kernel_launch(void* const* d_in, const int* in_sizes, int n_in,
                              void* d_out, int out_size) {
    const float* z1 = (const float*)d_in[0];
    const float* z2 = (const float*)d_in[1];
    float* out = (float*)d_out;

    cudaFuncSetAttribute(gemm_qk_kernel,
                         cudaFuncAttributeMaxDynamicSharedMemorySize, SMEM_BYTES);
    cudaFuncSetAttribute(gemm_av_kernel,
                         cudaFuncAttributeMaxDynamicSharedMemorySize, SMEM_BYTES);

    build_q_kernel<<<800, 256>>>(z1);
    build_kv_kernel<<<28160, 256>>>(z2);
    gemm_qk_kernel<<<dim3(NPAD / BN, M / BM), 64, SMEM_BYTES>>>();   // 88x5 = 440
    rowsum_kernel<<<dim3(4, M), 128>>>();                            // 640 small CTAs
    gemm_av_kernel<<<dim3(D / BN, M / BM), 64, SMEM_BYTES>>>(out);   // 80x5 = 400
}

// round 12
// speedup vs baseline: 1.0511x; 1.0211x over previous
#include <cuda_runtime.h>
#include <cuda_fp16.h>
#include <cstdint>

// ---------------- problem constants ----------------
constexpr int KC = 128, KH = 10, KW = 4;
constexpr int H = 100, W = 64;
constexpr int NH = 10, NW = 16;
constexpr int M = NH * NW;                 // 160 q rows
constexpr int HK = H - KH + 1;             // 91
constexpr int WK = W - KW + 1;             // 61
constexpr int NKV = HK * WK;               // 5551
constexpr int NPAD = 5632;                 // 88*64
constexpr int D = KC * KH * KW;            // 5120
constexpr int NT1 = NPAD / 64;             // 88 qk n-tiles

// ---------------- scratch ----------------
__device__ __half g_kv[(size_t)NPAD * D];      // [n][d] d-contig
__device__ __half g_q[M * D];
__device__ __half g_attn[M * NPAD];            // unnormalized exp(scores), pads = 0
__device__ float  g_rsum2[M][NT1];             // per-(row, n-tile) partial sums

// ---------------- ptx helpers ----------------
__device__ __forceinline__ uint32_t smem_u32(const void* p) {
    return (uint32_t)__cvta_generic_to_shared(p);
}
__device__ __forceinline__ void ldsm_x4(uint32_t& r0, uint32_t& r1, uint32_t& r2,
                                        uint32_t& r3, uint32_t a) {
    asm volatile("ldmatrix.sync.aligned.m8n8.x4.shared.b16 {%0,%1,%2,%3}, [%4];"
                 : "=r"(r0), "=r"(r1), "=r"(r2), "=r"(r3) : "r"(a));
}
__device__ __forceinline__ void ldsm_x4_t(uint32_t& r0, uint32_t& r1, uint32_t& r2,
                                          uint32_t& r3, uint32_t a) {
    asm volatile("ldmatrix.sync.aligned.m8n8.x4.trans.shared.b16 {%0,%1,%2,%3}, [%4];"
                 : "=r"(r0), "=r"(r1), "=r"(r2), "=r"(r3) : "r"(a));
}
__device__ __forceinline__ void mma16816(float* c, const uint32_t* a, const uint32_t* b) {
    asm volatile("mma.sync.aligned.m16n8k16.row.col.f32.f16.f16.f32 "
                 "{%0,%1,%2,%3}, {%4,%5,%6,%7}, {%8,%9}, {%0,%1,%2,%3};"
                 : "+f"(c[0]), "+f"(c[1]), "+f"(c[2]), "+f"(c[3])
                 : "r"(a[0]), "r"(a[1]), "r"(a[2]), "r"(a[3]),
                   "r"(b[0]), "r"(b[1]));
}
__device__ __forceinline__ void cpasync16(uint32_t s, const void* g) {
    asm volatile("cp.async.cg.shared.global [%0], [%1], 16;" :: "r"(s), "l"(g));
}
__device__ __forceinline__ void cpasync16_ca(uint32_t s, const void* g) {
    asm volatile("cp.async.ca.shared.global [%0], [%1], 16;" :: "r"(s), "l"(g));
}
#define CP_COMMIT() asm volatile("cp.async.commit_group;")
#define CP_WAIT(n)  asm volatile("cp.async.wait_group %0;" :: "n"(n))

// -------- kernel 1: build q + kv (merged, 16B stores for kv) --------
// kv groups: (n, c, ip) ip=0..4 covers rows i=2ip,2ip+1 -> 8 halves, 16B aligned.
constexpr int KV16  = NKV * KC * (KH / 2);             // 3,552,640
constexpr int PAD16 = (NPAD - NKV) * (D / 8);          // 51,840
constexpr int Q16   = M * KC * (KH / 2);               // 102,400
constexpr int BUILD_TOTAL = KV16 + PAD16 + Q16;        // 3,706,880

__global__ void build_all_kernel(const float* __restrict__ z1,
                                 const float* __restrict__ z2) {
    int idx = blockIdx.x * blockDim.x + threadIdx.x;
    if (idx < KV16) {
        int n   = idx / 640;                   // 640 = 128 c * 5 ip
        int rem = idx - n * 640;
        int c   = rem / 5;
        int ip  = rem - c * 5;
        int h   = n / WK;
        int w   = n - h * WK;
        const float* s0 = z2 + (c * H + h + 2 * ip) * W + w;
        const float* s1 = s0 + W;
        __half2 a0 = __floats2half2_rn(s0[0], s0[1]);
        __half2 a1 = __floats2half2_rn(s0[2], s0[3]);
        __half2 b0 = __floats2half2_rn(s1[0], s1[1]);
        __half2 b1 = __floats2half2_rn(s1[2], s1[3]);
        uint4 v;
        v.x = *reinterpret_cast<uint32_t*>(&a0);
        v.y = *reinterpret_cast<uint32_t*>(&a1);
        v.z = *reinterpret_cast<uint32_t*>(&b0);
        v.w = *reinterpret_cast<uint32_t*>(&b1);
        *reinterpret_cast<uint4*>(&g_kv[(size_t)n * D + c * 40 + ip * 8]) = v;
    } else if (idx < KV16 + PAD16) {
        int p   = idx - KV16;
        int pr  = p / (D / 8);
        int off = (p - pr * (D / 8)) * 8;
        *reinterpret_cast<uint4*>(&g_kv[(size_t)(NKV + pr) * D + off]) =
            make_uint4(0u, 0u, 0u, 0u);
    } else if (idx < BUILD_TOTAL) {
        int p   = idx - KV16 - PAD16;
        int m   = p / 640;
        int rem = p - m * 640;
        int c   = rem / 5;
        int ip  = rem - c * 5;
        int ih  = m >> 4;
        int iw  = m & 15;
        const float4 f0 = *reinterpret_cast<const float4*>(
            z1 + (c * H + ih * KH + 2 * ip) * W + iw * KW);
        const float4 f1 = *reinterpret_cast<const float4*>(
            z1 + (c * H + ih * KH + 2 * ip + 1) * W + iw * KW);
        __half2 a0 = __floats2half2_rn(f0.x, f0.y);
        __half2 a1 = __floats2half2_rn(f0.z, f0.w);
        __half2 b0 = __floats2half2_rn(f1.x, f1.y);
        __half2 b1 = __floats2half2_rn(f1.z, f1.w);
        uint4 v;
        v.x = *reinterpret_cast<uint32_t*>(&a0);
        v.y = *reinterpret_cast<uint32_t*>(&a1);
        v.z = *reinterpret_cast<uint32_t*>(&b0);
        v.w = *reinterpret_cast<uint32_t*>(&b1);
        *reinterpret_cast<uint4*>(&g_q[m * D + c * 40 + ip * 8]) = v;
    }
}

// -------- GEMM tiling: CTA 32(M) x 64(N), 64 threads = 2 warps (32x32 each) ----
constexpr int BM  = 32;
constexpr int BN  = 64;
constexpr int BK  = 64;
constexpr int LDS = 72;
constexpr int STAGES = 4;
constexpr int A_HALVES = BM * LDS;               // 2304
constexpr int B_HALVES = BN * LDS;               // 4608
constexpr int STAGE_HALVES = A_HALVES + B_HALVES;
constexpr int SMEM_BYTES = STAGES * STAGE_HALVES * 2;   // 55296

// ------ kernel 2: attn_unnorm = exp(q @ kv^T / D) + fused row partial sums ------
__global__ __launch_bounds__(64, 4) void gemm_qk_kernel() {
    extern __shared__ __align__(16) __half sm[];
    __shared__ float rsm[2][32];
    const int n0   = blockIdx.x * BN;
    const int m0   = blockIdx.y * BM;
    const int tid  = threadIdx.x;
    const int wn   = tid >> 5, lane = tid & 31;
    constexpr int KT = D / BK;                   // 80

    auto load_stage = [&](int s, int kt) {
        const int k0 = kt * BK;
        __half* As = sm + s * STAGE_HALVES;
        __half* Bs = As + A_HALVES;
#pragma unroll
        for (int i = 0; i < 4; i++) {
            int t = tid + i * 64;
            int r = t >> 3, c8 = (t & 7) << 3;
            cpasync16_ca(smem_u32(&As[r * LDS + c8]),
                         &g_q[(m0 + r) * D + k0 + c8]);
        }
#pragma unroll
        for (int i = 0; i < 8; i++) {
            int t = tid + i * 64;
            int r = t >> 3, c8 = (t & 7) << 3;
            cpasync16(smem_u32(&Bs[r * LDS + c8]),
                      &g_kv[(size_t)(n0 + r) * D + k0 + c8]);
        }
    };

#pragma unroll
    for (int s = 0; s < STAGES - 1; s++) { load_stage(s, s); CP_COMMIT(); }

    float acc[2][4][4] = {};
    uint32_t a[2][2][4], b[2][4][2];

    auto load_frags = [&](const __half* As, const __half* Bs, int ks, int buf) {
#pragma unroll
        for (int mi = 0; mi < 2; mi++) {
            int r = mi * 16 + (lane & 15);
            int c = ks * 16 + (lane >> 4) * 8;
            ldsm_x4(a[buf][mi][0], a[buf][mi][1], a[buf][mi][2], a[buf][mi][3],
                    smem_u32(&As[r * LDS + c]));
        }
#pragma unroll
        for (int nb = 0; nb < 2; nb++) {
            int r = wn * 32 + nb * 16 + (lane & 7) + (lane >> 4) * 8;
            int c = ks * 16 + ((lane >> 3) & 1) * 8;
            uint32_t r0, r1, r2, r3;
            ldsm_x4(r0, r1, r2, r3, smem_u32(&Bs[r * LDS + c]));
            b[buf][nb * 2][0] = r0; b[buf][nb * 2][1] = r1;
            b[buf][nb * 2 + 1][0] = r2; b[buf][nb * 2 + 1][1] = r3;
        }
    };

    for (int kt = 0; kt < KT; kt++) {
        CP_WAIT(STAGES - 2);
        __syncthreads();
        int nxt = kt + STAGES - 1;
        if (nxt < KT) load_stage(nxt & (STAGES - 1), nxt);
        CP_COMMIT();

        const __half* As = sm + (kt & (STAGES - 1)) * STAGE_HALVES;
        const __half* Bs = As + A_HALVES;
        load_frags(As, Bs, 0, 0);
#pragma unroll
        for (int ks = 0; ks < BK / 16; ks++) {
            const int cur = ks & 1;
            if (ks < BK / 16 - 1) load_frags(As, Bs, ks + 1, cur ^ 1);
#pragma unroll
            for (int mi = 0; mi < 2; mi++)
#pragma unroll
                for (int ni = 0; ni < 4; ni++)
                    mma16816(acc[mi][ni], a[cur][mi], b[cur][ni]);
        }
    }

    // epilogue: p = exp(s/D), mask pad cols, store fp16 + fused row partials
    const float scale = 1.0f / (float)D;
    float rp[2][2] = {};                         // [mi][row half]
#pragma unroll
    for (int mi = 0; mi < 2; mi++)
#pragma unroll
        for (int ni = 0; ni < 4; ni++) {
            int row = m0 + mi * 16 + (lane >> 2);
            int col = n0 + wn * 32 + ni * 8 + ((lane & 3) << 1);
            float p00 = (col     < NKV) ? __expf(acc[mi][ni][0] * scale) : 0.f;
            float p01 = (col + 1 < NKV) ? __expf(acc[mi][ni][1] * scale) : 0.f;
            float p10 = (col     < NKV) ? __expf(acc[mi][ni][2] * scale) : 0.f;
            float p11 = (col + 1 < NKV) ? __expf(acc[mi][ni][3] * scale) : 0.f;
            *reinterpret_cast<__half2*>(&g_attn[row * NPAD + col]) =
                __floats2half2_rn(p00, p01);
            *reinterpret_cast<__half2*>(&g_attn[(row + 8) * NPAD + col]) =
                __floats2half2_rn(p10, p11);
            rp[mi][0] += p00 + p01;
            rp[mi][1] += p10 + p11;
        }
    // reduce over the 4 lanes sharing each row (lane bits 0-1)
#pragma unroll
    for (int o = 1; o < 4; o <<= 1) {
#pragma unroll
        for (int mi = 0; mi < 2; mi++) {
            rp[mi][0] += __shfl_xor_sync(0xffffffffu, rp[mi][0], o);
            rp[mi][1] += __shfl_xor_sync(0xffffffffu, rp[mi][1], o);
        }
    }
    if ((lane & 3) == 0) {
        int r = lane >> 2;
#pragma unroll
        for (int mi = 0; mi < 2; mi++) {
            rsm[wn][mi * 16 + r]     = rp[mi][0];
            rsm[wn][mi * 16 + 8 + r] = rp[mi][1];
        }
    }
    __syncthreads();
    if (tid < 32)
        g_rsum2[m0 + tid][blockIdx.x] = rsm[0][tid] + rsm[1][tid];
}

// ---------------- kernel 3: out = (attn_unnorm @ kv) * inv[row] ----------------
__device__ __forceinline__ void store_out(float* __restrict__ out, int m, int d, float v) {
    int c   = d / 40;
    int rem = d - c * 40;
    int i   = rem >> 2;
    int j   = rem & 3;
    int ih  = m >> 4;
    int iw  = m & 15;
    out[(c * H + ih * KH + i) * W + iw * KW + j] = v;
}

__global__ __launch_bounds__(64, 4) void gemm_av_kernel(float* __restrict__ out) {
    extern __shared__ __align__(16) __half sm[];
    __shared__ float invs[32];
    const int n0   = blockIdx.x * BN;            // over D
    const int m0   = blockIdx.y * BM;
    const int tid  = threadIdx.x;
    const int wn   = tid >> 5, lane = tid & 31;
    constexpr int KT = NPAD / BK;                // 88

    // compute per-row inverse sums while the pipeline warms up
    if (tid < 32) {
        float s = 0.f;
#pragma unroll 8
        for (int t = 0; t < NT1; t++) s += g_rsum2[m0 + tid][t];
        invs[tid] = 1.0f / s;
    }

    auto load_stage = [&](int s, int kt) {
        const int k0 = kt * BK;
        __half* As = sm + s * STAGE_HALVES;
        __half* Bs = As + A_HALVES;
#pragma unroll
        for (int i = 0; i < 4; i++) {
            int t = tid + i * 64;
            int r = t >> 3, c8 = (t & 7) << 3;
            cpasync16_ca(smem_u32(&As[r * LDS + c8]),
                         &g_attn[(m0 + r) * NPAD + k0 + c8]);
        }
#pragma unroll
        for (int i = 0; i < 8; i++) {
            int t = tid + i * 64;
            int r = t >> 3, c8 = (t & 7) << 3;
            cpasync16(smem_u32(&Bs[r * LDS + c8]),
                      &g_kv[(size_t)(k0 + r) * D + n0 + c8]);
        }
    };

#pragma unroll
    for (int s = 0; s < STAGES - 1; s++) { load_stage(s, s); CP_COMMIT(); }

    float acc[2][4][4] = {};
    uint32_t a[2][2][4], b[2][4][2];

    auto load_frags = [&](const __half* As, const __half* Bs, int ks, int buf) {
#pragma unroll
        for (int mi = 0; mi < 2; mi++) {
            int r = mi * 16 + (lane & 15);
            int c = ks * 16 + (lane >> 4) * 8;
            ldsm_x4(a[buf][mi][0], a[buf][mi][1], a[buf][mi][2], a[buf][mi][3],
                    smem_u32(&As[r * LDS + c]));
        }
#pragma unroll
        for (int nb = 0; nb < 2; nb++) {
            int r = ks * 16 + (lane & 7) + ((lane >> 3) & 1) * 8;
            int c = wn * 32 + nb * 16 + (lane >> 4) * 8;
            uint32_t r0, r1, r2, r3;
            ldsm_x4_t(r0, r1, r2, r3, smem_u32(&Bs[r * LDS + c]));
            b[buf][nb * 2][0] = r0; b[buf][nb * 2][1] = r1;
            b[buf][nb * 2 + 1][0] = r2; b[buf][nb * 2 + 1][1] = r3;
        }
    };

    for (int kt = 0; kt < KT; kt++) {
        CP_WAIT(STAGES - 2);
        __syncthreads();
        int nxt = kt + STAGES - 1;
        if (nxt < KT) load_stage(nxt & (STAGES - 1), nxt);
        CP_COMMIT();

        const __half* As = sm + (kt & (STAGES - 1)) * STAGE_HALVES;
        const __half* Bs = As + A_HALVES;
        load_frags(As, Bs, 0, 0);
#pragma unroll
        for (int ks = 0; ks < BK / 16; ks++) {
            const int cur = ks & 1;
            if (ks < BK / 16 - 1) load_frags(As, Bs, ks + 1, cur ^ 1);
#pragma unroll
            for (int mi = 0; mi < 2; mi++)
#pragma unroll
                for (int ni = 0; ni < 4; ni++)
                    mma16816(acc[mi][ni], a[cur][mi], b[cur][ni]);
        }
    }

#pragma unroll
    for (int mi = 0; mi < 2; mi++) {
        int row = m0 + mi * 16 + (lane >> 2);
        const float inv0 = invs[mi * 16 + (lane >> 2)];
        const float inv1 = invs[mi * 16 + 8 + (lane >> 2)];
#pragma unroll
        for (int ni = 0; ni < 4; ni++) {
            int col = n0 + wn * 32 + ni * 8 + ((lane & 3) << 1);
            store_out(out, row,     col,     acc[mi][ni][0] * inv0);
            store_out(out, row,     col + 1, acc[mi][ni][1] * inv0);
            store_out(out, row + 8, col,     acc[mi][ni][2] * inv1);
            store_out(out, row + 8, col + 1, acc[mi][ni][3] * inv1);
        }
    }
}

// ---------------- launch ----------------
extern "C" void kernel_launch(void* const* d_in, const int* in_sizes, int n_in,
                              void* d_out, int out_size) {
    const float* z1 = (const float*)d_in[0];
    const float* z2 = (const float*)d_in[1];
    float* out = (float*)d_out;

    cudaFuncSetAttribute(gemm_qk_kernel,
                         cudaFuncAttributeMaxDynamicSharedMemorySize, SMEM_BYTES);
    cudaFuncSetAttribute(gemm_av_kernel,
                         cudaFuncAttributeMaxDynamicSharedMemorySize, SMEM_BYTES);

    build_all_kernel<<<(BUILD_TOTAL + 255) / 256, 256>>>(z1, z2);
    gemm_qk_kernel<<<dim3(NPAD / BN, M / BM), 64, SMEM_BYTES>>>();   // 88x5 = 440
    gemm_av_kernel<<<dim3(D / BN, M / BM), 64, SMEM_BYTES>>>(out);   // 80x5 = 400
}

// round 13
// speedup vs baseline: 1.8600x; 1.7697x over previous
#include <cuda_runtime.h>
#include <cuda_fp16.h>
#include <cstdint>

// ---------------- problem constants ----------------
constexpr int KC = 128, KH = 10, KW = 4;
constexpr int H = 100, W = 64;
constexpr int HW = H * W;                  // 6400
constexpr int NH = 10, NW = 16;
constexpr int M = NH * NW;                 // 160 q rows
constexpr int HK = H - KH + 1;             // 91
constexpr int WK = W - KW + 1;             // 61
constexpr int NKV = HK * WK;               // 5551
constexpr int NPAD = 5632;                 // 88*64
constexpr int D = KC * KH * KW;            // 5120
constexpr int NT1 = NPAD / 64;             // 88 qk n-tiles

// Feature ordering: d = (i*4+j)*128 + c   (ij-major, channel-fast)

// ---------------- scratch ----------------
__device__ __half g_z1t[(size_t)HW * KC];      // [hw][c] channel-fast
__device__ __half g_z2t[(size_t)HW * KC];
__device__ __half g_kv[(size_t)NPAD * D];      // [n][d]
__device__ __half g_q[M * D];
__device__ __half g_attn[M * NPAD];            // unnormalized exp(scores), pads = 0
__device__ float  g_rsum2[M][NT1];             // per-(row, n-tile) partial sums

// ---------------- ptx helpers ----------------
__device__ __forceinline__ uint32_t smem_u32(const void* p) {
    return (uint32_t)__cvta_generic_to_shared(p);
}
__device__ __forceinline__ void ldsm_x4(uint32_t& r0, uint32_t& r1, uint32_t& r2,
                                        uint32_t& r3, uint32_t a) {
    asm volatile("ldmatrix.sync.aligned.m8n8.x4.shared.b16 {%0,%1,%2,%3}, [%4];"
                 : "=r"(r0), "=r"(r1), "=r"(r2), "=r"(r3) : "r"(a));
}
__device__ __forceinline__ void ldsm_x4_t(uint32_t& r0, uint32_t& r1, uint32_t& r2,
                                          uint32_t& r3, uint32_t a) {
    asm volatile("ldmatrix.sync.aligned.m8n8.x4.trans.shared.b16 {%0,%1,%2,%3}, [%4];"
                 : "=r"(r0), "=r"(r1), "=r"(r2), "=r"(r3) : "r"(a));
}
__device__ __forceinline__ void mma16816(float* c, const uint32_t* a, const uint32_t* b) {
    asm volatile("mma.sync.aligned.m16n8k16.row.col.f32.f16.f16.f32 "
                 "{%0,%1,%2,%3}, {%4,%5,%6,%7}, {%8,%9}, {%0,%1,%2,%3};"
                 : "+f"(c[0]), "+f"(c[1]), "+f"(c[2]), "+f"(c[3])
                 : "r"(a[0]), "r"(a[1]), "r"(a[2]), "r"(a[3]),
                   "r"(b[0]), "r"(b[1]));
}
__device__ __forceinline__ void cpasync16(uint32_t s, const void* g) {
    asm volatile("cp.async.cg.shared.global [%0], [%1], 16;" :: "r"(s), "l"(g));
}
__device__ __forceinline__ void cpasync16_ca(uint32_t s, const void* g) {
    asm volatile("cp.async.ca.shared.global [%0], [%1], 16;" :: "r"(s), "l"(g));
}
#define CP_COMMIT() asm volatile("cp.async.commit_group;")
#define CP_WAIT(n)  asm volatile("cp.async.wait_group %0;" :: "n"(n))

// ------- kernel 0: transpose z1/z2 [c][hw] f32 -> [hw][c] f16 -------
__global__ __launch_bounds__(256) void transpose_kernel(const float* __restrict__ z1,
                                                        const float* __restrict__ z2) {
    __shared__ float tile[32][33];
    const float* src = blockIdx.z ? z2 : z1;
    __half* dst      = blockIdx.z ? g_z2t : g_z1t;
    const int hw0 = blockIdx.x * 32;
    const int c0  = blockIdx.y * 32;
    const int tx = threadIdx.x & 31;
    const int ty = threadIdx.x >> 5;               // 0..7
#pragma unroll
    for (int k = 0; k < 4; k++)
        tile[ty + 8 * k][tx] = src[(size_t)(c0 + ty + 8 * k) * HW + hw0 + tx];
    __syncthreads();
#pragma unroll
    for (int k = 0; k < 4; k++)
        dst[(size_t)(hw0 + ty + 8 * k) * KC + c0 + tx] =
            __float2half(tile[tx][ty + 8 * k]);
}

// ------- kernel 1: build q + kv, fully coalesced 16B chunks -------
// chunk index f = ij*16 + cp  (ij = i*4+j, cp = 16-byte chunk of channels)
constexpr int CH_ROW = D / 8;                          // 640 chunks per row
constexpr int KV16  = NKV * CH_ROW;                    // 3,552,640
constexpr int PAD16 = (NPAD - NKV) * CH_ROW;           // 51,840
constexpr int Q16   = M * CH_ROW;                      // 102,400
constexpr int BUILD_TOTAL = KV16 + PAD16 + Q16;        // 3,706,880

__global__ __launch_bounds__(256) void build_all_kernel() {
    int idx = blockIdx.x * blockDim.x + threadIdx.x;
    const uint4* z2t = reinterpret_cast<const uint4*>(g_z2t);
    const uint4* z1t = reinterpret_cast<const uint4*>(g_z1t);
    uint4* kv = reinterpret_cast<uint4*>(g_kv);
    uint4* q  = reinterpret_cast<uint4*>(g_q);
    if (idx < KV16) {
        int n  = idx / CH_ROW;
        int f  = idx - n * CH_ROW;
        int h  = n / WK;
        int w  = n - h * WK;
        int ij = f >> 4;
        int cp = f & 15;
        int i  = ij >> 2;
        int j  = ij & 3;
        kv[(size_t)n * CH_ROW + f] = z2t[((h + i) * W + w + j) * 16 + cp];
    } else if (idx < KV16 + PAD16) {
        int p = idx - KV16;
        kv[(size_t)NKV * CH_ROW + p] = make_uint4(0u, 0u, 0u, 0u);
    } else if (idx < BUILD_TOTAL) {
        int p  = idx - KV16 - PAD16;
        int m  = p / CH_ROW;
        int f  = p - m * CH_ROW;
        int ih = m >> 4;
        int iw = m & 15;
        int ij = f >> 4;
        int cp = f & 15;
        int i  = ij >> 2;
        int j  = ij & 3;
        q[(size_t)m * CH_ROW + f] = z1t[((ih * KH + i) * W + iw * KW + j) * 16 + cp];
    }
}

// -------- GEMM tiling: CTA 32(M) x 64(N), 64 threads = 2 warps (32x32 each) ----
constexpr int BM  = 32;
constexpr int BN  = 64;
constexpr int BK  = 64;
constexpr int LDS = 72;
constexpr int STAGES = 4;
constexpr int A_HALVES = BM * LDS;               // 2304
constexpr int B_HALVES = BN * LDS;               // 4608
constexpr int STAGE_HALVES = A_HALVES + B_HALVES;
constexpr int SMEM_BYTES = STAGES * STAGE_HALVES * 2;   // 55296

// ------ kernel 2: attn_unnorm = exp(q @ kv^T / D) + fused row partial sums ------
__global__ __launch_bounds__(64, 4) void gemm_qk_kernel() {
    extern __shared__ __align__(16) __half sm[];
    __shared__ float rsm[2][32];
    const int n0   = blockIdx.x * BN;
    const int m0   = blockIdx.y * BM;
    const int tid  = threadIdx.x;
    const int wn   = tid >> 5, lane = tid & 31;
    constexpr int KT = D / BK;                   // 80

    auto load_stage = [&](int s, int kt) {
        const int k0 = kt * BK;
        __half* As = sm + s * STAGE_HALVES;
        __half* Bs = As + A_HALVES;
#pragma unroll
        for (int i = 0; i < 4; i++) {
            int t = tid + i * 64;
            int r = t >> 3, c8 = (t & 7) << 3;
            cpasync16_ca(smem_u32(&As[r * LDS + c8]),
                         &g_q[(m0 + r) * D + k0 + c8]);
        }
#pragma unroll
        for (int i = 0; i < 8; i++) {
            int t = tid + i * 64;
            int r = t >> 3, c8 = (t & 7) << 3;
            cpasync16(smem_u32(&Bs[r * LDS + c8]),
                      &g_kv[(size_t)(n0 + r) * D + k0 + c8]);
        }
    };

#pragma unroll
    for (int s = 0; s < STAGES - 1; s++) { load_stage(s, s); CP_COMMIT(); }

    float acc[2][4][4] = {};
    uint32_t a[2][2][4], b[2][4][2];

    auto load_frags = [&](const __half* As, const __half* Bs, int ks, int buf) {
#pragma unroll
        for (int mi = 0; mi < 2; mi++) {
            int r = mi * 16 + (lane & 15);
            int c = ks * 16 + (lane >> 4) * 8;
            ldsm_x4(a[buf][mi][0], a[buf][mi][1], a[buf][mi][2], a[buf][mi][3],
                    smem_u32(&As[r * LDS + c]));
        }
#pragma unroll
        for (int nb = 0; nb < 2; nb++) {
            int r = wn * 32 + nb * 16 + (lane & 7) + (lane >> 4) * 8;
            int c = ks * 16 + ((lane >> 3) & 1) * 8;
            uint32_t r0, r1, r2, r3;
            ldsm_x4(r0, r1, r2, r3, smem_u32(&Bs[r * LDS + c]));
            b[buf][nb * 2][0] = r0; b[buf][nb * 2][1] = r1;
            b[buf][nb * 2 + 1][0] = r2; b[buf][nb * 2 + 1][1] = r3;
        }
    };

    for (int kt = 0; kt < KT; kt++) {
        CP_WAIT(STAGES - 2);
        __syncthreads();
        int nxt = kt + STAGES - 1;
        if (nxt < KT) load_stage(nxt & (STAGES - 1), nxt);
        CP_COMMIT();

        const __half* As = sm + (kt & (STAGES - 1)) * STAGE_HALVES;
        const __half* Bs = As + A_HALVES;
        load_frags(As, Bs, 0, 0);
#pragma unroll
        for (int ks = 0; ks < BK / 16; ks++) {
            const int cur = ks & 1;
            if (ks < BK / 16 - 1) load_frags(As, Bs, ks + 1, cur ^ 1);
#pragma unroll
            for (int mi = 0; mi < 2; mi++)
#pragma unroll
                for (int ni = 0; ni < 4; ni++)
                    mma16816(acc[mi][ni], a[cur][mi], b[cur][ni]);
        }
    }

    // epilogue: p = exp(s/D), mask pad cols, store fp16 + fused row partials
    const float scale = 1.0f / (float)D;
    float rp[2][2] = {};
#pragma unroll
    for (int mi = 0; mi < 2; mi++)
#pragma unroll
        for (int ni = 0; ni < 4; ni++) {
            int row = m0 + mi * 16 + (lane >> 2);
            int col = n0 + wn * 32 + ni * 8 + ((lane & 3) << 1);
            float p00 = (col     < NKV) ? __expf(acc[mi][ni][0] * scale) : 0.f;
            float p01 = (col + 1 < NKV) ? __expf(acc[mi][ni][1] * scale) : 0.f;
            float p10 = (col     < NKV) ? __expf(acc[mi][ni][2] * scale) : 0.f;
            float p11 = (col + 1 < NKV) ? __expf(acc[mi][ni][3] * scale) : 0.f;
            *reinterpret_cast<__half2*>(&g_attn[row * NPAD + col]) =
                __floats2half2_rn(p00, p01);
            *reinterpret_cast<__half2*>(&g_attn[(row + 8) * NPAD + col]) =
                __floats2half2_rn(p10, p11);
            rp[mi][0] += p00 + p01;
            rp[mi][1] += p10 + p11;
        }
#pragma unroll
    for (int o = 1; o < 4; o <<= 1) {
#pragma unroll
        for (int mi = 0; mi < 2; mi++) {
            rp[mi][0] += __shfl_xor_sync(0xffffffffu, rp[mi][0], o);
            rp[mi][1] += __shfl_xor_sync(0xffffffffu, rp[mi][1], o);
        }
    }
    if ((lane & 3) == 0) {
        int r = lane >> 2;
#pragma unroll
        for (int mi = 0; mi < 2; mi++) {
            rsm[wn][mi * 16 + r]     = rp[mi][0];
            rsm[wn][mi * 16 + 8 + r] = rp[mi][1];
        }
    }
    __syncthreads();
    if (tid < 32)
        g_rsum2[m0 + tid][blockIdx.x] = rsm[0][tid] + rsm[1][tid];
}

// ---------------- kernel 3: out = (attn_unnorm @ kv) * inv[row] ----------------
// feature decode for d = ij*128 + c
__device__ __forceinline__ void store_out(float* __restrict__ out, int m, int d, float v) {
    int ij = d >> 7;
    int c  = d & 127;
    int i  = ij >> 2;
    int j  = ij & 3;
    int ih = m >> 4;
    int iw = m & 15;
    out[(c * H + ih * KH + i) * W + iw * KW + j] = v;
}

__global__ __launch_bounds__(64, 4) void gemm_av_kernel(float* __restrict__ out) {
    extern __shared__ __align__(16) __half sm[];
    __shared__ float invs[32];
    const int n0   = blockIdx.x * BN;            // over D
    const int m0   = blockIdx.y * BM;
    const int tid  = threadIdx.x;
    const int wn   = tid >> 5, lane = tid & 31;
    constexpr int KT = NPAD / BK;                // 88

    if (tid < 32) {
        float s = 0.f;
#pragma unroll 8
        for (int t = 0; t < NT1; t++) s += g_rsum2[m0 + tid][t];
        invs[tid] = 1.0f / s;
    }

    auto load_stage = [&](int s, int kt) {
        const int k0 = kt * BK;
        __half* As = sm + s * STAGE_HALVES;
        __half* Bs = As + A_HALVES;
#pragma unroll
        for (int i = 0; i < 4; i++) {
            int t = tid + i * 64;
            int r = t >> 3, c8 = (t & 7) << 3;
            cpasync16_ca(smem_u32(&As[r * LDS + c8]),
                         &g_attn[(m0 + r) * NPAD + k0 + c8]);
        }
#pragma unroll
        for (int i = 0; i < 8; i++) {
            int t = tid + i * 64;
            int r = t >> 3, c8 = (t & 7) << 3;
            cpasync16(smem_u32(&Bs[r * LDS + c8]),
                      &g_kv[(size_t)(k0 + r) * D + n0 + c8]);
        }
    };

#pragma unroll
    for (int s = 0; s < STAGES - 1; s++) { load_stage(s, s); CP_COMMIT(); }

    float acc[2][4][4] = {};
    uint32_t a[2][2][4], b[2][4][2];

    auto load_frags = [&](const __half* As, const __half* Bs, int ks, int buf) {
#pragma unroll
        for (int mi = 0; mi < 2; mi++) {
            int r = mi * 16 + (lane & 15);
            int c = ks * 16 + (lane >> 4) * 8;
            ldsm_x4(a[buf][mi][0], a[buf][mi][1], a[buf][mi][2], a[buf][mi][3],
                    smem_u32(&As[r * LDS + c]));
        }
#pragma unroll
        for (int nb = 0; nb < 2; nb++) {
            int r = ks * 16 + (lane & 7) + ((lane >> 3) & 1) * 8;
            int c = wn * 32 + nb * 16 + (lane >> 4) * 8;
            uint32_t r0, r1, r2, r3;
            ldsm_x4_t(r0, r1, r2, r3, smem_u32(&Bs[r * LDS + c]));
            b[buf][nb * 2][0] = r0; b[buf][nb * 2][1] = r1;
            b[buf][nb * 2 + 1][0] = r2; b[buf][nb * 2 + 1][1] = r3;
        }
    };

    for (int kt = 0; kt < KT; kt++) {
        CP_WAIT(STAGES - 2);
        __syncthreads();
        int nxt = kt + STAGES - 1;
        if (nxt < KT) load_stage(nxt & (STAGES - 1), nxt);
        CP_COMMIT();

        const __half* As = sm + (kt & (STAGES - 1)) * STAGE_HALVES;
        const __half* Bs = As + A_HALVES;
        load_frags(As, Bs, 0, 0);
#pragma unroll
        for (int ks = 0; ks < BK / 16; ks++) {
            const int cur = ks & 1;
            if (ks < BK / 16 - 1) load_frags(As, Bs, ks + 1, cur ^ 1);
#pragma unroll
            for (int mi = 0; mi < 2; mi++)
#pragma unroll
                for (int ni = 0; ni < 4; ni++)
                    mma16816(acc[mi][ni], a[cur][mi], b[cur][ni]);
        }
    }

#pragma unroll
    for (int mi = 0; mi < 2; mi++) {
        int row = m0 + mi * 16 + (lane >> 2);
        const float inv0 = invs[mi * 16 + (lane >> 2)];
        const float inv1 = invs[mi * 16 + 8 + (lane >> 2)];
#pragma unroll
        for (int ni = 0; ni < 4; ni++) {
            int col = n0 + wn * 32 + ni * 8 + ((lane & 3) << 1);
            store_out(out, row,     col,     acc[mi][ni][0] * inv0);
            store_out(out, row,     col + 1, acc[mi][ni][1] * inv0);
            store_out(out, row + 8, col,     acc[mi][ni][2] * inv1);
            store_out(out, row + 8, col + 1, acc[mi][ni][3] * inv1);
        }
    }
}

// ---------------- launch ----------------
extern "C" void kernel_launch(void* const* d_in, const int* in_sizes, int n_in,
                              void* d_out, int out_size) {
    const float* z1 = (const float*)d_in[0];
    const float* z2 = (const float*)d_in[1];
    float* out = (float*)d_out;

    cudaFuncSetAttribute(gemm_qk_kernel,
                         cudaFuncAttributeMaxDynamicSharedMemorySize, SMEM_BYTES);
    cudaFuncSetAttribute(gemm_av_kernel,
                         cudaFuncAttributeMaxDynamicSharedMemorySize, SMEM_BYTES);

    transpose_kernel<<<dim3(HW / 32, KC / 32, 2), 256>>>(z1, z2);
    build_all_kernel<<<(BUILD_TOTAL + 255) / 256, 256>>>();
    gemm_qk_kernel<<<dim3(NPAD / BN, M / BM), 64, SMEM_BYTES>>>();   // 88x5 = 440
    gemm_av_kernel<<<dim3(D / BN, M / BM), 64, SMEM_BYTES>>>(out);   // 80x5 = 400
}